// round 16
// baseline (speedup 1.0000x reference)
#include <cuda_runtime.h>

#define NHID 32
#define BM   64
#define TK   32

// scratch for support = x @ W  (allocation-free rule: __device__ global)
static __device__ float g_support[10000 * NHID];

__device__ __forceinline__ float4 loadA4(const float* __restrict__ A, int M, int K, int r, int k)
{
    float4 v = make_float4(0.f, 0.f, 0.f, 0.f);
    if (r < M) {
        const float* p = A + (long long)r * K + k;
        if (k + 4 <= K) {
            v = *reinterpret_cast<const float4*>(p);
        } else {
            if (k + 0 < K) v.x = p[0];
            if (k + 1 < K) v.y = p[1];
            if (k + 2 < K) v.z = p[2];
            if (k + 3 < K) v.w = p[3];
        }
    }
    return v;
}

__device__ __forceinline__ float4 loadB4(const float* __restrict__ B, int K, int k, int c)
{
    float4 v = make_float4(0.f, 0.f, 0.f, 0.f);
    if (k < K) v = *reinterpret_cast<const float4*>(B + (long long)k * NHID + c);
    return v;
}

// C[M,32] = A[M,K] @ B[K,32] (+ bias). Register-tiled fp32, BM=64, TK=32,
// thread tile 4 rows x 2 cols, 256 threads, single-stage register prefetch.
template <bool ADD_BIAS>
__global__ __launch_bounds__(256)
void gemm_n32(const float* __restrict__ A, const float* __restrict__ B,
              const float* __restrict__ bias, float* __restrict__ C,
              int M, int K)
{
    __shared__ float Ash[TK][BM + 4];     // [kk][row], stride 68 floats (16B-aligned rows)
    __shared__ float Bsh[TK][NHID + 4];   // [kk][col], stride 36 floats (16B-aligned rows)

    const int tid = threadIdx.x;
    const int m0  = blockIdx.x * BM;

    // output mapping: cols = cg*2 .. +1, rows = rg*4 .. +3
    const int cg = tid & 15;
    const int rg = tid >> 4;

    // global-load mapping
    const int a_row0 = tid >> 3;          // rows 0..31 of the tile
    const int a_row1 = (tid + 256) >> 3;  // rows 32..63
    const int a_f4   = tid & 7;           // float4 index along k (0..7)
    const int b_row  = tid >> 3;          // k-row of B tile
    const int b_f4   = tid & 7;           // float4 col group (only 0..7 used, 32 cols)

    float acc[4][2];
#pragma unroll
    for (int i = 0; i < 4; i++) { acc[i][0] = 0.f; acc[i][1] = 0.f; }

    const int ntiles = (K + TK - 1) / TK;

    float4 areg0 = loadA4(A, M, K, m0 + a_row0, a_f4 * 4);
    float4 areg1 = loadA4(A, M, K, m0 + a_row1, a_f4 * 4);
    float4 breg  = loadB4(B, K, b_row, b_f4 * 4);

#define STS_TILE() do {                                                     \
        Ash[a_f4*4+0][a_row0] = areg0.x; Ash[a_f4*4+1][a_row0] = areg0.y;   \
        Ash[a_f4*4+2][a_row0] = areg0.z; Ash[a_f4*4+3][a_row0] = areg0.w;   \
        Ash[a_f4*4+0][a_row1] = areg1.x; Ash[a_f4*4+1][a_row1] = areg1.y;   \
        Ash[a_f4*4+2][a_row1] = areg1.z; Ash[a_f4*4+3][a_row1] = areg1.w;   \
        *reinterpret_cast<float4*>(&Bsh[b_row][b_f4*4]) = breg;             \
    } while (0)

    STS_TILE();
    __syncthreads();

    for (int t = 0; t < ntiles; t++) {
        if (t + 1 < ntiles) {
            const int k = (t + 1) * TK;
            areg0 = loadA4(A, M, K, m0 + a_row0, k + a_f4 * 4);
            areg1 = loadA4(A, M, K, m0 + a_row1, k + a_f4 * 4);
            breg  = loadB4(B, K, k + b_row, b_f4 * 4);
        }

#pragma unroll
        for (int kk = 0; kk < TK; kk++) {
            float4 a  = *reinterpret_cast<const float4*>(&Ash[kk][rg * 4]);
            float2 bb = *reinterpret_cast<const float2*>(&Bsh[kk][cg * 2]);
            acc[0][0] = fmaf(a.x, bb.x, acc[0][0]); acc[0][1] = fmaf(a.x, bb.y, acc[0][1]);
            acc[1][0] = fmaf(a.y, bb.x, acc[1][0]); acc[1][1] = fmaf(a.y, bb.y, acc[1][1]);
            acc[2][0] = fmaf(a.z, bb.x, acc[2][0]); acc[2][1] = fmaf(a.z, bb.y, acc[2][1]);
            acc[3][0] = fmaf(a.w, bb.x, acc[3][0]); acc[3][1] = fmaf(a.w, bb.y, acc[3][1]);
        }

        __syncthreads();
        if (t + 1 < ntiles) {
            STS_TILE();
            __syncthreads();
        }
    }
#undef STS_TILE

#pragma unroll
    for (int i = 0; i < 4; i++) {
        const int r = m0 + rg * 4 + i;
        if (r < M) {
#pragma unroll
            for (int j = 0; j < 2; j++) {
                const int c = cg * 2 + j;
                float v = acc[i][j];
                if (ADD_BIAS) v += bias[c];
                C[(long long)r * NHID + c] = v;
            }
        }
    }
}

// Student-t soft assignment: one warp per row of z.
// d2 = |z|^2 - 2 z.mu_j + |mu_j|^2 ; q = (1/(1+d2/a+1e-8))^(a+1)/2, row-normalized.
__global__ void student_t_q(const float* __restrict__ z, const float* __restrict__ mu,
                            float* __restrict__ q, int M, int KC)
{
    const int row  = blockIdx.x * (blockDim.x >> 5) + (threadIdx.x >> 5);
    const int lane = threadIdx.x & 31;
    if (row >= M) return;

    const float zv = z[(long long)row * NHID + lane];
    float z2 = zv * zv;
#pragma unroll
    for (int o = 16; o > 0; o >>= 1) z2 += __shfl_xor_sync(0xffffffffu, z2, o);

    float s = 0.f, qmine = 0.f;
    for (int j = 0; j < KC; j++) {
        const float m = mu[j * NHID + lane];
        float dot = zv * m;
        float m2  = m * m;
#pragma unroll
        for (int o = 16; o > 0; o >>= 1) {
            dot += __shfl_xor_sync(0xffffffffu, dot, o);
            m2  += __shfl_xor_sync(0xffffffffu, m2,  o);
        }
        const float d2 = z2 - 2.f * dot + m2;
        float qq = 1.f / (1.f + d2 * 5.0f + 1e-8f);   // d2 / ALPHA, ALPHA = 0.2
        qq = powf(qq, 1.2f) * 0.5f;                   // q^(ALPHA+1) / 2
        s += qq;
        if (lane == j) qmine = qq;
    }
    if (lane < KC) q[(long long)row * KC + lane] = qmine / s;
}

extern "C" void kernel_launch(void* const* d_in, const int* in_sizes, int n_in,
                              void* d_out, int out_size)
{
    const float* x   = (const float*)d_in[0];   // [N, NFEAT]
    const float* adj = (const float*)d_in[1];   // [N, N]
    const float* W   = (const float*)d_in[2];   // [NFEAT, NHID]
    const float* b   = (const float*)d_in[3];   // [NHID]
    const float* mu  = (const float*)d_in[4];   // [KC, NHID]

    const int nhid  = in_sizes[3];              // 32
    const int nfeat = in_sizes[2] / nhid;       // 3000
    const int n     = in_sizes[0] / nfeat;      // 10000
    const int kc    = in_sizes[4] / nhid;       // 10

    float* z = (float*)d_out;                   // [n, 32]
    float* q = z + (size_t)n * nhid;            // [n, kc]

    float* support = nullptr;
    cudaGetSymbolAddress((void**)&support, g_support);

    const int grid = (n + BM - 1) / BM;         // 157 blocks -> full chip
    gemm_n32<false><<<grid, 256>>>(x, W, nullptr, support, n, nfeat);
    gemm_n32<true ><<<grid, 256>>>(adj, support, b, z, n, n);

    const int rows_per_block = 256 / 32;
    student_t_q<<<(n + rows_per_block - 1) / rows_per_block, 256>>>(z, mu, q, n, kc);
}

// round 17
// speedup vs baseline: 1.0649x; 1.0649x over previous
#include <cuda_runtime.h>

#define NHID 32
#define BM   64
#define TK   32
#define MAXN 10000
#define MAXS 4

// scratch (allocation-free rule: __device__ globals)
static __device__ float g_support[MAXN * NHID];
static __device__ float g_part[MAXS * MAXN * NHID];

// ---------------- f32x2 helpers (FFMA2 path, PTX-only per SASS quickref) ----
__device__ __forceinline__ unsigned long long pack2(float x, float y)
{
    unsigned long long r;
    asm("mov.b64 %0, {%1, %2};" : "=l"(r) : "f"(x), "f"(y));
    return r;
}
__device__ __forceinline__ void fma2(unsigned long long& d,
                                     unsigned long long a, unsigned long long b)
{
    asm("fma.rn.f32x2 %0, %1, %2, %0;" : "+l"(d) : "l"(a), "l"(b));
}
__device__ __forceinline__ void unpack2(unsigned long long v, float& lo, float& hi)
{
    asm("mov.b64 {%0, %1}, %2;" : "=f"(lo), "=f"(hi) : "l"(v));
}

// guarded vector loads ------------------------------------------------------
__device__ __forceinline__ float4 loadA4(const float* __restrict__ A, int M, int K,
                                         int kend, int r, int k)
{
    float4 v = make_float4(0.f, 0.f, 0.f, 0.f);
    if (r < M && k < kend) {
        const float* p = A + (long long)r * K + k;
        if (k + 4 <= kend) {
            v = *reinterpret_cast<const float4*>(p);
        } else {
            if (k + 0 < kend) v.x = p[0];
            if (k + 1 < kend) v.y = p[1];
            if (k + 2 < kend) v.z = p[2];
        }
    }
    return v;
}
__device__ __forceinline__ float4 loadB4(const float* __restrict__ B, int kend, int k, int c)
{
    float4 v = make_float4(0.f, 0.f, 0.f, 0.f);
    if (k < kend) v = *reinterpret_cast<const float4*>(B + (long long)k * NHID + c);
    return v;
}

// Cpart[slice][M,32] += A[M, kbeg:kend] @ B[kbeg:kend, 32]
// BM=64, TK=32, 256 threads, double-buffered smem, FFMA2 inner loop,
// B tile stored DUPLICATED so (b,b) broadcast pairs are one LDS.128.
__global__ __launch_bounds__(256, 2)
void gemm_n32_split(const float* __restrict__ A, const float* __restrict__ B,
                    float* __restrict__ Cpart, int M, int K, int Ks)
{
    __shared__ float Ash[2][TK][BM + 4];        // [buf][kk][row]
    __shared__ float Bdup[2][TK][2 * NHID + 4]; // [buf][kk][2*col(+dup)]

    const int tid  = threadIdx.x;
    const int m0   = blockIdx.x * BM;
    const int kbeg = blockIdx.y * Ks;
    const int kend = min(K, kbeg + Ks);

    const int cg = tid & 15;   // col pair:  cg*2, cg*2+1
    const int rg = tid >> 4;   // row quad:  rg*4 .. +3

    const int a_row0 = tid >> 3;
    const int a_row1 = a_row0 + 32;
    const int a_f4   = tid & 7;
    const int b_row  = tid >> 3;
    const int b_f4   = tid & 7;

    unsigned long long acc00 = 0ull, acc01 = 0ull, acc10 = 0ull, acc11 = 0ull;

    const int nt = (kend - kbeg + TK - 1) / TK;

    float4 areg0 = loadA4(A, M, K, kend, m0 + a_row0, kbeg + a_f4 * 4);
    float4 areg1 = loadA4(A, M, K, kend, m0 + a_row1, kbeg + a_f4 * 4);
    float4 breg  = loadB4(B, kend, kbeg + b_row, b_f4 * 4);

#define STS_TILE(buf) do {                                                          \
        Ash[buf][a_f4*4+0][a_row0] = areg0.x; Ash[buf][a_f4*4+1][a_row0] = areg0.y; \
        Ash[buf][a_f4*4+2][a_row0] = areg0.z; Ash[buf][a_f4*4+3][a_row0] = areg0.w; \
        Ash[buf][a_f4*4+0][a_row1] = areg1.x; Ash[buf][a_f4*4+1][a_row1] = areg1.y; \
        Ash[buf][a_f4*4+2][a_row1] = areg1.z; Ash[buf][a_f4*4+3][a_row1] = areg1.w; \
        unsigned long long* bd =                                                    \
            reinterpret_cast<unsigned long long*>(&Bdup[buf][b_row][b_f4 * 8]);     \
        bd[0] = pack2(breg.x, breg.x); bd[1] = pack2(breg.y, breg.y);               \
        bd[2] = pack2(breg.z, breg.z); bd[3] = pack2(breg.w, breg.w);               \
    } while (0)

    STS_TILE(0);
    __syncthreads();

    for (int t = 0; t < nt; t++) {
        const int cur = t & 1;
        if (t + 1 < nt) {
            const int k = kbeg + (t + 1) * TK;
            areg0 = loadA4(A, M, K, kend, m0 + a_row0, k + a_f4 * 4);
            areg1 = loadA4(A, M, K, kend, m0 + a_row1, k + a_f4 * 4);
            breg  = loadB4(B, kend, k + b_row, b_f4 * 4);
        }

#pragma unroll
        for (int kk = 0; kk < TK; kk++) {
            const ulonglong2 a =
                *reinterpret_cast<const ulonglong2*>(&Ash[cur][kk][rg * 4]);
            const ulonglong2 b =
                *reinterpret_cast<const ulonglong2*>(&Bdup[cur][kk][cg * 4]);
            fma2(acc00, a.x, b.x);   // rows 0,1  col c0
            fma2(acc01, a.y, b.x);   // rows 2,3  col c0
            fma2(acc10, a.x, b.y);   // rows 0,1  col c1
            fma2(acc11, a.y, b.y);   // rows 2,3  col c1
        }

        if (t + 1 < nt) STS_TILE(cur ^ 1);
        __syncthreads();
    }
#undef STS_TILE

    float v[4][2];
    unpack2(acc00, v[0][0], v[1][0]); unpack2(acc01, v[2][0], v[3][0]);
    unpack2(acc10, v[0][1], v[1][1]); unpack2(acc11, v[2][1], v[3][1]);

    float* Cs = Cpart + (size_t)blockIdx.y * M * NHID;
#pragma unroll
    for (int i = 0; i < 4; i++) {
        const int r = m0 + rg * 4 + i;
        if (r < M) {
            Cs[(long long)r * NHID + cg * 2 + 0] = v[i][0];
            Cs[(long long)r * NHID + cg * 2 + 1] = v[i][1];
        }
    }
}

// out = sum_s part[s] (+ bias), float4-vectorized. total4 = M*32/4.
__global__ void reduce_slices(const float* __restrict__ part,
                              const float* __restrict__ bias,
                              float* __restrict__ out,
                              int total4, int stride4, int S)
{
    const int i = blockIdx.x * blockDim.x + threadIdx.x;
    if (i >= total4) return;
    const float4* p = reinterpret_cast<const float4*>(part);
    float4 s = p[i];
    for (int sl = 1; sl < S; sl++) {
        const float4 t = p[i + (size_t)sl * stride4];
        s.x += t.x; s.y += t.y; s.z += t.z; s.w += t.w;
    }
    if (bias) {
        const float4 bb = reinterpret_cast<const float4*>(bias)[i & 7];
        s.x += bb.x; s.y += bb.y; s.z += bb.z; s.w += bb.w;
    }
    reinterpret_cast<float4*>(out)[i] = s;
}

// Student-t soft assignment: one warp per row of z.
__global__ void student_t_q(const float* __restrict__ z, const float* __restrict__ mu,
                            float* __restrict__ q, int M, int KC)
{
    const int row  = blockIdx.x * (blockDim.x >> 5) + (threadIdx.x >> 5);
    const int lane = threadIdx.x & 31;
    if (row >= M) return;

    const float zv = z[(long long)row * NHID + lane];
    float z2 = zv * zv;
#pragma unroll
    for (int o = 16; o > 0; o >>= 1) z2 += __shfl_xor_sync(0xffffffffu, z2, o);

    float s = 0.f, qmine = 0.f;
    for (int j = 0; j < KC; j++) {
        const float m = mu[j * NHID + lane];
        float dot = zv * m;
        float m2  = m * m;
#pragma unroll
        for (int o = 16; o > 0; o >>= 1) {
            dot += __shfl_xor_sync(0xffffffffu, dot, o);
            m2  += __shfl_xor_sync(0xffffffffu, m2,  o);
        }
        const float d2 = z2 - 2.f * dot + m2;
        float qq = 1.f / (1.f + d2 * 5.0f + 1e-8f);
        qq = powf(qq, 1.2f) * 0.5f;
        s += qq;
        if (lane == j) qmine = qq;
    }
    if (lane < KC) q[(long long)row * KC + lane] = qmine / s;
}

extern "C" void kernel_launch(void* const* d_in, const int* in_sizes, int n_in,
                              void* d_out, int out_size)
{
    const float* x   = (const float*)d_in[0];   // [N, NFEAT]
    const float* adj = (const float*)d_in[1];   // [N, N]
    const float* W   = (const float*)d_in[2];   // [NFEAT, NHID]
    const float* b   = (const float*)d_in[3];   // [NHID]
    const float* mu  = (const float*)d_in[4];   // [KC, NHID]

    const int nhid  = in_sizes[3];              // 32
    const int nfeat = in_sizes[2] / nhid;       // 3000
    const int n     = in_sizes[0] / nfeat;      // 10000
    const int kc    = in_sizes[4] / nhid;       // 10

    float* z = (float*)d_out;                   // [n, 32]
    float* q = z + (size_t)n * nhid;            // [n, kc]

    float *support = nullptr, *part = nullptr;
    cudaGetSymbolAddress((void**)&support, g_support);
    cudaGetSymbolAddress((void**)&part,    g_part);

    const int grid    = (n + BM - 1) / BM;      // 157 m-tiles
    const int total4  = n * nhid / 4;
    const int stride4 = n * nhid / 4;
    const int rthreads = 256;
    const int rblocks  = (total4 + rthreads - 1) / rthreads;

    // GEMM1: support = x @ W   (K = 3000, split 2)
    {
        const int S  = 2;
        const int Ks = (((nfeat + S - 1) / S) + 3) & ~3;
        gemm_n32_split<<<dim3(grid, S), 256>>>(x, W, part, n, nfeat, Ks);
        reduce_slices<<<rblocks, rthreads>>>(part, nullptr, support, total4, stride4, S);
    }

    // GEMM2: z = adj @ support + b   (K = 10000, split 4)
    {
        const int S  = 4;
        const int Ks = (((n + S - 1) / S) + 3) & ~3;
        gemm_n32_split<<<dim3(grid, S), 256>>>(adj, support, part, n, n, Ks);
        reduce_slices<<<rblocks, rthreads>>>(part, b, z, total4, stride4, S);
    }

    const int rows_per_block = 256 / 32;
    student_t_q<<<(n + rows_per_block - 1) / rows_per_block, 256>>>(z, mu, q, n, kc);
}